// round 5
// baseline (speedup 1.0000x reference)
#include <cuda_runtime.h>
#include <cuda_bf16.h>
#include <cstdint>
#include <cstddef>

#define DI __device__ __forceinline__

static constexpr int NROWS = 8192;   // rows of inputs (M)
static constexpr int KDIM  = 4096;   // inner dim (K)
static constexpr int NOUT  = 4096;   // output features (N)
// index = f32(0.9) * f32(16777215) rounds to exactly 15099493.0 -> frac = 0,
// thresh = ascending order statistic at 0-based rank 15099493 of |w|.
static constexpr unsigned long long QRANK = 15099493ull;

// ---------------- scratch (device globals; no allocation allowed) ----------
__device__ __align__(16) unsigned short g_Ahi[(size_t)NROWS * KDIM];
__device__ __align__(16) unsigned short g_Alo[(size_t)NROWS * KDIM];
__device__ __align__(16) unsigned short g_Bhi[(size_t)NOUT * KDIM];
__device__ __align__(16) unsigned short g_Blo[(size_t)NOUT * KDIM];
__device__ unsigned g_hist1[65536];
__device__ unsigned g_hist2[65536];
__device__ unsigned g_sel[2];        // [0] = hi16 bucket, [1] = remaining rank
__device__ unsigned g_threshbits;    // f32 bit pattern of |w| threshold

// ---------------- small PTX helpers ----------------------------------------
DI uint32_t smem_u32(const void* p) {
    uint32_t r;
    asm("{ .reg .u64 t; cvta.to.shared.u64 t, %1; cvt.u32.u64 %0, t; }"
        : "=r"(r) : "l"(p));
    return r;
}

DI void cp16(uint32_t sdst, const void* gsrc) {
    asm volatile("cp.async.cg.shared.global [%0], [%1], 16;"
                 :: "r"(sdst), "l"(gsrc) : "memory");
}
DI void cp_commit() { asm volatile("cp.async.commit_group;" ::: "memory"); }
DI void cp_wait0()  { asm volatile("cp.async.wait_group 0;" ::: "memory"); }

DI void ldm_x4(uint32_t* r, uint32_t addr) {
    asm volatile("ldmatrix.sync.aligned.m8n8.x4.shared.b16 {%0,%1,%2,%3}, [%4];"
                 : "=r"(r[0]), "=r"(r[1]), "=r"(r[2]), "=r"(r[3]) : "r"(addr));
}

DI void mma_bf16(float* d, const uint32_t* a, const uint32_t* b) {
    asm volatile(
        "mma.sync.aligned.m16n8k16.row.col.f32.bf16.bf16.f32 "
        "{%0,%1,%2,%3}, {%4,%5,%6,%7}, {%8,%9}, {%0,%1,%2,%3};"
        : "+f"(d[0]), "+f"(d[1]), "+f"(d[2]), "+f"(d[3])
        : "r"(a[0]), "r"(a[1]), "r"(a[2]), "r"(a[3]), "r"(b[0]), "r"(b[1]));
}

// ---------------- threshold: exact order statistic via 2-pass radix --------
__global__ void zero_hists_k() {
    int i = blockIdx.x * blockDim.x + threadIdx.x;
    if (i < 65536) { g_hist1[i] = 0u; g_hist2[i] = 0u; }
}

__global__ void hist_pass1_k(const float4* __restrict__ w, int n4) {
    for (int i = blockIdx.x * blockDim.x + threadIdx.x; i < n4;
         i += gridDim.x * blockDim.x) {
        float4 v = w[i];
        atomicAdd(&g_hist1[__float_as_uint(fabsf(v.x)) >> 16], 1u);
        atomicAdd(&g_hist1[__float_as_uint(fabsf(v.y)) >> 16], 1u);
        atomicAdd(&g_hist1[__float_as_uint(fabsf(v.z)) >> 16], 1u);
        atomicAdd(&g_hist1[__float_as_uint(fabsf(v.w)) >> 16], 1u);
    }
}

__global__ void select_pass1_k() {
    __shared__ unsigned partial[256];
    unsigned tid = threadIdx.x;
    unsigned sum = 0;
    for (int j = 0; j < 256; j++) sum += g_hist1[tid * 256 + j];
    partial[tid] = sum;
    __syncthreads();
    if (tid == 0) {
        unsigned long long cum = 0;
        int seg = 0;
        for (; seg < 256; seg++) {
            if (cum + partial[seg] > QRANK) break;
            cum += partial[seg];
        }
        unsigned b = seg * 256;
        for (int j = 0; j < 256; j++) {
            unsigned h = g_hist1[seg * 256 + j];
            if (cum + h > QRANK) { b = seg * 256 + j; break; }
            cum += h;
        }
        g_sel[0] = b;
        g_sel[1] = (unsigned)(QRANK - cum);
    }
}

__global__ void hist_pass2_k(const float4* __restrict__ w, int n4) {
    unsigned bucket = g_sel[0];
    for (int i = blockIdx.x * blockDim.x + threadIdx.x; i < n4;
         i += gridDim.x * blockDim.x) {
        float4 v = w[i];
        unsigned u;
        u = __float_as_uint(fabsf(v.x)); if ((u >> 16) == bucket) atomicAdd(&g_hist2[u & 0xFFFFu], 1u);
        u = __float_as_uint(fabsf(v.y)); if ((u >> 16) == bucket) atomicAdd(&g_hist2[u & 0xFFFFu], 1u);
        u = __float_as_uint(fabsf(v.z)); if ((u >> 16) == bucket) atomicAdd(&g_hist2[u & 0xFFFFu], 1u);
        u = __float_as_uint(fabsf(v.w)); if ((u >> 16) == bucket) atomicAdd(&g_hist2[u & 0xFFFFu], 1u);
    }
}

__global__ void select_pass2_k() {
    __shared__ unsigned partial[256];
    unsigned tid = threadIdx.x;
    unsigned sum = 0;
    for (int j = 0; j < 256; j++) sum += g_hist2[tid * 256 + j];
    partial[tid] = sum;
    __syncthreads();
    if (tid == 0) {
        unsigned long long rank = g_sel[1];
        unsigned long long cum = 0;
        int seg = 0;
        for (; seg < 256; seg++) {
            if (cum + partial[seg] > rank) break;
            cum += partial[seg];
        }
        unsigned lo = seg * 256;
        for (int j = 0; j < 256; j++) {
            unsigned h = g_hist2[seg * 256 + j];
            if (cum + h > rank) { lo = seg * 256 + j; break; }
            cum += h;
        }
        g_threshbits = (g_sel[0] << 16) | lo;
    }
}

// ---------------- split-bf16 conversion ------------------------------------
DI void split_bf16(float f, unsigned short& h, unsigned short& l) {
    __nv_bfloat16 hb = __float2bfloat16(f);                 // RN
    float rest = f - __bfloat162float(hb);                  // exact
    __nv_bfloat16 lb = __float2bfloat16(rest);
    h = __bfloat16_as_ushort(hb);
    l = __bfloat16_as_ushort(lb);
}

__global__ void conv_inputs_k(const float4* __restrict__ x) {
    const size_t n4 = (size_t)NROWS * KDIM / 4;
    for (size_t i = blockIdx.x * (size_t)blockDim.x + threadIdx.x; i < n4;
         i += (size_t)gridDim.x * blockDim.x) {
        float4 v = x[i];
        ushort4 h, l;
        split_bf16(v.x, h.x, l.x);
        split_bf16(v.y, h.y, l.y);
        split_bf16(v.z, h.z, l.z);
        split_bf16(v.w, h.w, l.w);
        reinterpret_cast<ushort4*>(g_Ahi)[i] = h;
        reinterpret_cast<ushort4*>(g_Alo)[i] = l;
    }
}

__global__ void conv_weight_k(const float4* __restrict__ w) {
    const unsigned tb = g_threshbits;
    const size_t n4 = (size_t)NOUT * KDIM / 4;
    for (size_t i = blockIdx.x * (size_t)blockDim.x + threadIdx.x; i < n4;
         i += (size_t)gridDim.x * blockDim.x) {
        float4 v = w[i];
        float m0 = (__float_as_uint(fabsf(v.x)) >= tb) ? v.x : 0.0f;
        float m1 = (__float_as_uint(fabsf(v.y)) >= tb) ? v.y : 0.0f;
        float m2 = (__float_as_uint(fabsf(v.z)) >= tb) ? v.z : 0.0f;
        float m3 = (__float_as_uint(fabsf(v.w)) >= tb) ? v.w : 0.0f;
        ushort4 h, l;
        split_bf16(m0, h.x, l.x);
        split_bf16(m1, h.y, l.y);
        split_bf16(m2, h.z, l.z);
        split_bf16(m3, h.w, l.w);
        reinterpret_cast<ushort4*>(g_Bhi)[i] = h;
        reinterpret_cast<ushort4*>(g_Blo)[i] = l;
    }
}

// ---------------- GEMM: mma.sync (portable, sm_80+ PTX) ---------------------
// Tile: 128(M) x 128(N), K chunks of 64. 4 smem tiles (Ahi/Alo/Bhi/Blo),
// each 128 rows x 128B (SW128 swizzle), double buffered. 256 threads.
// Warp layout: 4 (M) x 2 (N); warp tile 32(M) x 64(N).
static constexpr int TILE_BYTES  = 128 * 128;                 // 16 KB
static constexpr int STAGE_BYTES = 4 * TILE_BYTES;            // 64 KB
static constexpr unsigned GEMM_SMEM = 2048 + 2 * STAGE_BYTES; // 130 KB

DI void cp_tile(const unsigned short* __restrict__ g, int r0, int k0,
                uint32_t sdst, int tid) {
#pragma unroll
    for (int t = 0; t < 4; ++t) {
        int i = t * 256 + tid;           // 0..1023
        int row = i >> 3;                // 0..127
        int c16 = i & 7;                 // 16B column within 128B row
        const char* src =
            (const char*)(g + (size_t)(r0 + row) * KDIM + k0) + c16 * 16;
        uint32_t off = (uint32_t)(row * 128 + c16 * 16);
        off ^= (off >> 3) & 0x70;        // SW128 swizzle
        cp16(sdst + off, src);
    }
}

DI void cp_chunk(int c, uint32_t sdst, int m0, int n0, int tid) {
    int k0 = c * 64;
    cp_tile(g_Ahi, m0, k0, sdst, tid);
    cp_tile(g_Alo, m0, k0, sdst + TILE_BYTES, tid);
    cp_tile(g_Bhi, n0, k0, sdst + 2 * TILE_BYTES, tid);
    cp_tile(g_Blo, n0, k0, sdst + 3 * TILE_BYTES, tid);
}

__global__ void __launch_bounds__(256, 1)
topkast_gemm_k(const float* __restrict__ bias, float* __restrict__ out) {
    extern __shared__ char smem[];
    const uint32_t sbase = smem_u32(smem);
    const uint32_t tile_base = (sbase + 32 + 1023) & ~1023u;
    const int tid = threadIdx.x;
    const int wid = tid >> 5;
    const int lane = tid & 31;
    const int m0 = blockIdx.y * 128;
    const int n0 = blockIdx.x * 128;
    const int NCHUNK = KDIM / 64;     // 64

    const int wm = (wid & 3) * 32;    // warp m offset within tile
    const int wn = (wid >> 2) * 64;   // warp n offset within tile

    float acc[2][8][4];
#pragma unroll
    for (int a = 0; a < 2; ++a)
#pragma unroll
        for (int bq = 0; bq < 8; ++bq)
#pragma unroll
            for (int r = 0; r < 4; ++r) acc[a][bq][r] = 0.0f;

    cp_chunk(0, tile_base, m0, n0, tid);
    cp_commit();

    for (int c = 0; c < NCHUNK; ++c) {
        cp_wait0();
        __syncthreads();
        if (c + 1 < NCHUNK) {
            cp_chunk(c + 1, tile_base + (uint32_t)((c + 1) & 1) * STAGE_BYTES,
                     m0, n0, tid);
            cp_commit();
        }
        const uint32_t b = tile_base + (uint32_t)(c & 1) * STAGE_BYTES;

#pragma unroll
        for (int ks = 0; ks < 4; ++ks) {
            uint32_t ahf[2][4], alf[2][4], bhf[4][4], blf[4][4];
            // A fragments (m16k16 per mtile):
            //   lanes 0-7:(m0-7,klo) 8-15:(m8-15,klo) 16-23:(m0-7,khi) 24-31:(m8-15,khi)
            {
                uint32_t arow = (uint32_t)(wm + (lane & 15));
                uint32_t k8 = (uint32_t)(ks * 2 + (lane >> 4));
#pragma unroll
                for (int mt = 0; mt < 2; ++mt) {
                    uint32_t off = (arow + mt * 16) * 128 + k8 * 16;
                    off ^= (off >> 3) & 0x70;
                    ldm_x4(ahf[mt], b + off);
                    ldm_x4(alf[mt], b + TILE_BYTES + off);
                }
            }
            // B fragments (two n8 groups per x4):
            //   lanes 0-7:(n0-7,klo) 8-15:(n0-7,khi) 16-23:(n8-15,klo) 24-31:(n8-15,khi)
            {
                uint32_t nrow = (uint32_t)(wn + ((lane >> 4) << 3) + (lane & 7));
                uint32_t k8 = (uint32_t)(ks * 2 + ((lane >> 3) & 1));
#pragma unroll
                for (int np = 0; np < 4; ++np) {
                    uint32_t off = (nrow + np * 16) * 128 + k8 * 16;
                    off ^= (off >> 3) & 0x70;
                    ldm_x4(bhf[np], b + 2 * TILE_BYTES + off);
                    ldm_x4(blf[np], b + 3 * TILE_BYTES + off);
                }
            }
#pragma unroll
            for (int mt = 0; mt < 2; ++mt) {
#pragma unroll
                for (int ng = 0; ng < 8; ++ng) {
                    const uint32_t* bh = &bhf[ng >> 1][(ng & 1) * 2];
                    const uint32_t* bl = &blf[ng >> 1][(ng & 1) * 2];
                    mma_bf16(acc[mt][ng], ahf[mt], bh);   // Ah*Bh
                    mma_bf16(acc[mt][ng], alf[mt], bh);   // Al*Bh
                    mma_bf16(acc[mt][ng], ahf[mt], bl);   // Ah*Bl
                }
            }
        }
    }

    // epilogue: fragment c0,c1 -> (row lane/4, cols 2*(lane%4)+{0,1});
    //           c2,c3 -> row+8
#pragma unroll
    for (int mt = 0; mt < 2; ++mt) {
#pragma unroll
        for (int ng = 0; ng < 8; ++ng) {
            int m = m0 + wm + mt * 16 + (lane >> 2);
            int n = n0 + wn + ng * 8 + (lane & 3) * 2;
            float bx = bias[n], by = bias[n + 1];
            float2 v0 = make_float2(acc[mt][ng][0] + bx, acc[mt][ng][1] + by);
            float2 v1 = make_float2(acc[mt][ng][2] + bx, acc[mt][ng][3] + by);
            *reinterpret_cast<float2*>(&out[(size_t)m * NOUT + n]) = v0;
            *reinterpret_cast<float2*>(&out[(size_t)(m + 8) * NOUT + n]) = v1;
        }
    }
}

// ---------------- entry -----------------------------------------------------
extern "C" void kernel_launch(void* const* d_in, const int* in_sizes, int n_in,
                              void* d_out, int out_size) {
    const float* inputs = nullptr;
    const float* weight = nullptr;
    const float* bias = nullptr;
    for (int i = 0; i < n_in; ++i) {
        if (in_sizes[i] == NROWS * KDIM)      inputs = (const float*)d_in[i];
        else if (in_sizes[i] == NOUT * KDIM)  weight = (const float*)d_in[i];
        else if (in_sizes[i] == NOUT)         bias   = (const float*)d_in[i];
    }
    float* out = (float*)d_out;

    const int w4 = NOUT * KDIM / 4;

    zero_hists_k<<<256, 256>>>();
    hist_pass1_k<<<2048, 256>>>((const float4*)weight, w4);
    select_pass1_k<<<1, 256>>>();
    hist_pass2_k<<<2048, 256>>>((const float4*)weight, w4);
    select_pass2_k<<<1, 256>>>();

    conv_inputs_k<<<8192, 256>>>((const float4*)inputs);
    conv_weight_k<<<4096, 256>>>((const float4*)weight);

    cudaFuncSetAttribute(topkast_gemm_k,
                         cudaFuncAttributeMaxDynamicSharedMemorySize, GEMM_SMEM);
    dim3 grid(NOUT / 128, NROWS / 128);   // (32, 64)
    topkast_gemm_k<<<grid, 256, GEMM_SMEM>>>(bias, out);

    (void)out_size;
}

// round 10
// speedup vs baseline: 1.0735x; 1.0735x over previous
#include <cuda_runtime.h>
#include <cuda_bf16.h>
#include <cstdint>
#include <cstddef>

#define DI __device__ __forceinline__

static constexpr int NROWS = 8192;   // rows of inputs (M)
static constexpr int KDIM  = 4096;   // inner dim (K)
static constexpr int NOUT  = 4096;   // output features (N)
// index = f32(0.9) * f32(16777215) rounds to exactly 15099493.0 -> frac = 0,
// thresh = ascending order statistic at 0-based rank 15099493 of |w|.
static constexpr unsigned long long QRANK = 15099493ull;

// ---------------- scratch (device globals; no allocation allowed) ----------
__device__ __align__(16) unsigned short g_Ahi[(size_t)NROWS * KDIM];
__device__ __align__(16) unsigned short g_Alo[(size_t)NROWS * KDIM];
__device__ __align__(16) unsigned short g_Bhi[(size_t)NOUT * KDIM];
__device__ __align__(16) unsigned short g_Blo[(size_t)NOUT * KDIM];
__device__ unsigned g_hist1[65536];
__device__ unsigned g_hist2[65536];
__device__ unsigned g_sel[2];        // [0] = hi16 bucket, [1] = remaining rank
__device__ unsigned g_threshbits;    // f32 bit pattern of |w| threshold

// ---------------- small PTX helpers ----------------------------------------
DI uint32_t smem_u32(const void* p) {
    uint32_t r;
    asm("{ .reg .u64 t; cvta.to.shared.u64 t, %1; cvt.u32.u64 %0, t; }"
        : "=r"(r) : "l"(p));
    return r;
}

DI void cp16(uint32_t sdst, const void* gsrc) {
    asm volatile("cp.async.cg.shared.global [%0], [%1], 16;"
                 :: "r"(sdst), "l"(gsrc) : "memory");
}
DI void cp_commit() { asm volatile("cp.async.commit_group;" ::: "memory"); }
DI void cp_wait0()  { asm volatile("cp.async.wait_group 0;" ::: "memory"); }

DI void ldm_x4(uint32_t* r, uint32_t addr) {
    asm volatile("ldmatrix.sync.aligned.m8n8.x4.shared.b16 {%0,%1,%2,%3}, [%4];"
                 : "=r"(r[0]), "=r"(r[1]), "=r"(r[2]), "=r"(r[3]) : "r"(addr));
}

DI void mma_bf16(float* d, const uint32_t* a, const uint32_t* b) {
    asm volatile(
        "mma.sync.aligned.m16n8k16.row.col.f32.bf16.bf16.f32 "
        "{%0,%1,%2,%3}, {%4,%5,%6,%7}, {%8,%9}, {%0,%1,%2,%3};"
        : "+f"(d[0]), "+f"(d[1]), "+f"(d[2]), "+f"(d[3])
        : "r"(a[0]), "r"(a[1]), "r"(a[2]), "r"(a[3]), "r"(b[0]), "r"(b[1]));
}

DI uint32_t elect_one() {
    uint32_t p;
    asm volatile(
        "{\n\t.reg .pred p;\n\t"
        "elect.sync _|p, 0xFFFFFFFF;\n\t"
        "selp.b32 %0, 1, 0, p;\n\t}"
        : "=r"(p));
    return p;
}

DI void mbar_init(uint32_t addr, uint32_t count) {
    asm volatile("mbarrier.init.shared.b64 [%0], %1;"
                 :: "r"(addr), "r"(count) : "memory");
}

DI void mbar_wait_parity(uint32_t addr, uint32_t parity) {
    asm volatile(
        "{\n\t.reg .pred P1;\n\t"
        "WAIT_LOOP_%=:\n\t"
        "mbarrier.try_wait.parity.acquire.cta.shared::cta.b64 P1, [%0], %1, 0x989680;\n\t"
        "@P1 bra.uni WAIT_DONE_%=;\n\t"
        "bra.uni WAIT_LOOP_%=;\n\t"
        "WAIT_DONE_%=:\n\t}"
        :: "r"(addr), "r"(parity) : "memory");
}

// ---------------- threshold: exact order statistic via 2-pass radix --------
__global__ void zero_hists_k() {
    int i = blockIdx.x * blockDim.x + threadIdx.x;
    if (i < 65536) { g_hist1[i] = 0u; g_hist2[i] = 0u; }
}

__global__ void hist_pass1_k(const float4* __restrict__ w, int n4) {
    for (int i = blockIdx.x * blockDim.x + threadIdx.x; i < n4;
         i += gridDim.x * blockDim.x) {
        float4 v = w[i];
        atomicAdd(&g_hist1[__float_as_uint(fabsf(v.x)) >> 16], 1u);
        atomicAdd(&g_hist1[__float_as_uint(fabsf(v.y)) >> 16], 1u);
        atomicAdd(&g_hist1[__float_as_uint(fabsf(v.z)) >> 16], 1u);
        atomicAdd(&g_hist1[__float_as_uint(fabsf(v.w)) >> 16], 1u);
    }
}

__global__ void select_pass1_k() {
    __shared__ unsigned partial[256];
    unsigned tid = threadIdx.x;
    unsigned sum = 0;
    for (int j = 0; j < 256; j++) sum += g_hist1[tid * 256 + j];
    partial[tid] = sum;
    __syncthreads();
    if (tid == 0) {
        unsigned long long cum = 0;
        int seg = 0;
        for (; seg < 256; seg++) {
            if (cum + partial[seg] > QRANK) break;
            cum += partial[seg];
        }
        unsigned b = seg * 256;
        for (int j = 0; j < 256; j++) {
            unsigned h = g_hist1[seg * 256 + j];
            if (cum + h > QRANK) { b = seg * 256 + j; break; }
            cum += h;
        }
        g_sel[0] = b;
        g_sel[1] = (unsigned)(QRANK - cum);
    }
}

__global__ void hist_pass2_k(const float4* __restrict__ w, int n4) {
    unsigned bucket = g_sel[0];
    for (int i = blockIdx.x * blockDim.x + threadIdx.x; i < n4;
         i += gridDim.x * blockDim.x) {
        float4 v = w[i];
        unsigned u;
        u = __float_as_uint(fabsf(v.x)); if ((u >> 16) == bucket) atomicAdd(&g_hist2[u & 0xFFFFu], 1u);
        u = __float_as_uint(fabsf(v.y)); if ((u >> 16) == bucket) atomicAdd(&g_hist2[u & 0xFFFFu], 1u);
        u = __float_as_uint(fabsf(v.z)); if ((u >> 16) == bucket) atomicAdd(&g_hist2[u & 0xFFFFu], 1u);
        u = __float_as_uint(fabsf(v.w)); if ((u >> 16) == bucket) atomicAdd(&g_hist2[u & 0xFFFFu], 1u);
    }
}

__global__ void select_pass2_k() {
    __shared__ unsigned partial[256];
    unsigned tid = threadIdx.x;
    unsigned sum = 0;
    for (int j = 0; j < 256; j++) sum += g_hist2[tid * 256 + j];
    partial[tid] = sum;
    __syncthreads();
    if (tid == 0) {
        unsigned long long rank = g_sel[1];
        unsigned long long cum = 0;
        int seg = 0;
        for (; seg < 256; seg++) {
            if (cum + partial[seg] > rank) break;
            cum += partial[seg];
        }
        unsigned lo = seg * 256;
        for (int j = 0; j < 256; j++) {
            unsigned h = g_hist2[seg * 256 + j];
            if (cum + h > rank) { lo = seg * 256 + j; break; }
            cum += h;
        }
        g_threshbits = (g_sel[0] << 16) | lo;
    }
}

// ---------------- split-bf16 conversion ------------------------------------
DI void split_bf16(float f, unsigned short& h, unsigned short& l) {
    __nv_bfloat16 hb = __float2bfloat16(f);                 // RN
    float rest = f - __bfloat162float(hb);                  // exact
    __nv_bfloat16 lb = __float2bfloat16(rest);
    h = __bfloat16_as_ushort(hb);
    l = __bfloat16_as_ushort(lb);
}

__global__ void conv_inputs_k(const float4* __restrict__ x) {
    const size_t n4 = (size_t)NROWS * KDIM / 4;
    for (size_t i = blockIdx.x * (size_t)blockDim.x + threadIdx.x; i < n4;
         i += (size_t)gridDim.x * blockDim.x) {
        float4 v = x[i];
        ushort4 h, l;
        split_bf16(v.x, h.x, l.x);
        split_bf16(v.y, h.y, l.y);
        split_bf16(v.z, h.z, l.z);
        split_bf16(v.w, h.w, l.w);
        reinterpret_cast<ushort4*>(g_Ahi)[i] = h;
        reinterpret_cast<ushort4*>(g_Alo)[i] = l;
    }
}

__global__ void conv_weight_k(const float4* __restrict__ w) {
    const unsigned tb = g_threshbits;
    const size_t n4 = (size_t)NOUT * KDIM / 4;
    for (size_t i = blockIdx.x * (size_t)blockDim.x + threadIdx.x; i < n4;
         i += (size_t)gridDim.x * blockDim.x) {
        float4 v = w[i];
        float m0 = (__float_as_uint(fabsf(v.x)) >= tb) ? v.x : 0.0f;
        float m1 = (__float_as_uint(fabsf(v.y)) >= tb) ? v.y : 0.0f;
        float m2 = (__float_as_uint(fabsf(v.z)) >= tb) ? v.z : 0.0f;
        float m3 = (__float_as_uint(fabsf(v.w)) >= tb) ? v.w : 0.0f;
        ushort4 h, l;
        split_bf16(m0, h.x, l.x);
        split_bf16(m1, h.y, l.y);
        split_bf16(m2, h.z, l.z);
        split_bf16(m3, h.w, l.w);
        reinterpret_cast<ushort4*>(g_Bhi)[i] = h;
        reinterpret_cast<ushort4*>(g_Blo)[i] = l;
    }
}

// ---------------- GEMM (dual path) ------------------------------------------
// Tile: 128(M) x 128(N), K chunks of 64. 4 smem tiles (Ahi/Alo/Bhi/Blo),
// each 128 rows x 128B (SW128 swizzle).
static constexpr int TILE_BYTES  = 128 * 128;                 // 16 KB
static constexpr int STAGE_BYTES = 4 * TILE_BYTES;            // 64 KB
static constexpr int NCHUNK = KDIM / 64;                      // 64

#if defined(__CUDA_ARCH__) && defined(__CUDA_ARCH_FEAT_SM103_ALL)
// ===================== tcgen05 path: 256 threads, serialized =================
// Minimal example-faithful shape (test_2cta_mma_bf16 / test_mma_iter):
// plain LDG+STS -> __syncthreads -> fence.proxy.async -> MMAs -> commit ->
// mbarrier wait. Single buffer; 66KB smem + 128 TMEM cols so 2 CTAs/SM
// co-reside and one CTA's load phase overlaps the other's MMA phase.
static constexpr unsigned GEMM_SMEM = 1024 + STAGE_BYTES;     // 66.5 KB

// idesc (kind::f16): dtype F32, a/b BF16, N=128, M=128
static constexpr uint32_t GEMM_IDESC =
    (1u << 4) | (1u << 7) | (1u << 10) | ((128u / 8) << 17) | ((128u / 16) << 24);

DI unsigned long long make_desc(uint32_t addr) {
    // SW128 K-major: layout=2, version=1, SBO=64, LBO=1
    return 0x4000404000010000ULL | ((unsigned long long)(addr >> 4) & 0x3FFFULL);
}

DI void ld_tile(const unsigned short* __restrict__ g, int r0, int k0,
                char* sdst, int tid) {
#pragma unroll
    for (int t = 0; t < 4; ++t) {
        int i = t * 256 + tid;           // 0..1023
        int row = i >> 3;                // 0..127
        int c16 = i & 7;                 // 16B column within 128B row
        uint4 v = reinterpret_cast<const uint4*>(
                      g + (size_t)(r0 + row) * KDIM + k0)[c16];
        uint32_t off = (uint32_t)(row * 128 + c16 * 16);
        off ^= (off >> 3) & 0x70;        // SW128 swizzle
        *reinterpret_cast<uint4*>(sdst + off) = v;
    }
}

DI void mma_f16(uint32_t d_tmem, unsigned long long a_desc,
                unsigned long long b_desc, uint32_t en) {
    uint32_t z = 0u;
    asm volatile(
        "{\n\t.reg .pred p;\n\t"
        "setp.ne.u32 p, %5, 0;\n\t"
        "tcgen05.mma.cta_group::1.kind::f16 [%0], %1, %2, %3, {%4,%4,%4,%4}, p;\n\t}"
        :: "r"(d_tmem), "l"(a_desc), "l"(b_desc), "r"(GEMM_IDESC),
           "r"(z), "r"(en) : "memory");
}

__global__ void __launch_bounds__(256, 1)
topkast_gemm_k(const float* __restrict__ bias, float* __restrict__ out) {
    extern __shared__ char smem[];
    const uint32_t sbase = smem_u32(smem);
    const uint32_t tile_base = (sbase + 32 + 1023) & ~1023u;
    char* tiles = smem + (tile_base - sbase);
    const uint32_t mbar = sbase + 8;
    const int tid = threadIdx.x;
    const int wid = tid >> 5;
    const int lid = tid & 31;
    const int m0 = blockIdx.y * 128;
    const int n0 = blockIdx.x * 128;

    // Alloc 128 TMEM cols from warp 0 only; no relinquish (warps that later
    // tcgen05.ld must keep the permit).  D occupies cols 0..127.
    if (wid == 0) {
        asm volatile(
            "tcgen05.alloc.cta_group::1.sync.aligned.shared::cta.b32 [%0], %1;"
            :: "r"(sbase), "r"(128u) : "memory");
    }
    if (tid == 0) mbar_init(mbar, 1);
    __syncthreads();

    uint32_t tmem;
    asm volatile("ld.shared.b32 %0, [%1];" : "=r"(tmem) : "r"(sbase));
    uint32_t leader = (wid == 0) ? elect_one() : 0u;

    const unsigned long long dAh = make_desc(tile_base);
    const unsigned long long dAl = make_desc(tile_base + TILE_BYTES);
    const unsigned long long dBh = make_desc(tile_base + 2 * TILE_BYTES);
    const unsigned long long dBl = make_desc(tile_base + 3 * TILE_BYTES);

    for (int c = 0; c < NCHUNK; ++c) {
        const int k0 = c * 64;
        ld_tile(g_Ahi, m0, k0, tiles, tid);
        ld_tile(g_Alo, m0, k0, tiles + TILE_BYTES, tid);
        ld_tile(g_Bhi, n0, k0, tiles + 2 * TILE_BYTES, tid);
        ld_tile(g_Blo, n0, k0, tiles + 3 * TILE_BYTES, tid);
        __syncthreads();
        asm volatile("fence.proxy.async.shared::cta;" ::: "memory");

        if (leader) {
#pragma unroll
            for (int ks = 0; ks < 4; ++ks)
                mma_f16(tmem, dAh + 2 * ks, dBh + 2 * ks,
                        (c == 0 && ks == 0) ? 0u : 1u);
#pragma unroll
            for (int ks = 0; ks < 4; ++ks)
                mma_f16(tmem, dAh + 2 * ks, dBl + 2 * ks, 1u);
#pragma unroll
            for (int ks = 0; ks < 4; ++ks)
                mma_f16(tmem, dAl + 2 * ks, dBh + 2 * ks, 1u);
            asm volatile(
                "tcgen05.commit.cta_group::1.mbarrier::arrive::one.shared::cluster.b64 [%0];"
                :: "r"(mbar) : "memory");
        }
        // chunk c is completion #c+1 on the mbar -> wait parity c&1.
        mbar_wait_parity(mbar, (uint32_t)(c & 1));
    }

    asm volatile("tcgen05.fence::after_thread_sync;" ::: "memory");

    // epilogue: warp w -> subpartition rows (w&3)*32, column half (w>>2)*64
    {
        const int m = m0 + (wid & 3) * 32 + lid;
        const int ch = (wid >> 2) * 64;
        float4* orow = reinterpret_cast<float4*>(out + (size_t)m * NOUT + n0);
        const float4* brow = reinterpret_cast<const float4*>(bias + n0);
#pragma unroll
        for (int q = 0; q < 2; ++q) {
            const int cb = ch + q * 32;
            uint32_t r[32];
            asm volatile(
                "tcgen05.ld.sync.aligned.32x32b.x32.b32 "
                "{%0, %1, %2, %3, %4, %5, %6, %7, "
                " %8, %9, %10, %11, %12, %13, %14, %15, "
                " %16, %17, %18, %19, %20, %21, %22, %23, "
                " %24, %25, %26, %27, %28, %29, %30, %31}, [%32];"
                : "=r"(r[0]), "=r"(r[1]), "=r"(r[2]), "=r"(r[3]),
                  "=r"(r[4]), "=r"(r[5]), "=r"(r[6]), "=r"(r[7]),
                  "=r"(r[8]), "=r"(r[9]), "=r"(r[10]), "=r"(r[11]),
                  "=r"(r[12]), "=r"(r[13]), "=r"(r[14]), "=r"(r[15]),
                  "=r"(r[16]), "=r"(r[17]), "=r"(r[18]), "=r"(r[19]),
                  "=r"(r[20]), "=r"(r[21]), "=r"(r[22]), "=r"(r[23]),
                  "=r"(r[24]), "=r"(r[25]), "=r"(r[26]), "=r"(r[27]),
                  "=r"(r[28]), "=r"(r[29]), "=r"(r[30]), "=r"(r[31])
                : "r"(tmem + cb));
            asm volatile("tcgen05.wait::ld.sync.aligned;" ::: "memory");
#pragma unroll
            for (int j = 0; j < 8; ++j) {
                float4 bv = brow[cb / 4 + j];
                float4 v;
                v.x = __uint_as_float(r[4 * j + 0]) + bv.x;
                v.y = __uint_as_float(r[4 * j + 1]) + bv.y;
                v.z = __uint_as_float(r[4 * j + 2]) + bv.z;
                v.w = __uint_as_float(r[4 * j + 3]) + bv.w;
                orow[cb / 4 + j] = v;
            }
        }
    }
    asm volatile("tcgen05.fence::before_thread_sync;" ::: "memory");
    __syncthreads();
    if (wid == 0) {
        asm volatile("tcgen05.dealloc.cta_group::1.sync.aligned.b32 %0, %1;"
                     :: "r"(tmem), "r"(128u));
    }
}

#else
// ===================== mma.sync fallback: 256 threads (R5-proven) ============
static constexpr unsigned GEMM_SMEM = 2048 + 2 * STAGE_BYTES; // 130 KB

DI void cp_tile(const unsigned short* __restrict__ g, int r0, int k0,
                uint32_t sdst, int tid) {
#pragma unroll
    for (int t = 0; t < 4; ++t) {
        int i = t * 256 + tid;           // 0..1023
        int row = i >> 3;
        int c16 = i & 7;
        const char* src =
            (const char*)(g + (size_t)(r0 + row) * KDIM + k0) + c16 * 16;
        uint32_t off = (uint32_t)(row * 128 + c16 * 16);
        off ^= (off >> 3) & 0x70;
        cp16(sdst + off, src);
    }
}

DI void cp_chunk(int c, uint32_t sdst, int m0, int n0, int tid) {
    int k0 = c * 64;
    cp_tile(g_Ahi, m0, k0, sdst, tid);
    cp_tile(g_Alo, m0, k0, sdst + TILE_BYTES, tid);
    cp_tile(g_Bhi, n0, k0, sdst + 2 * TILE_BYTES, tid);
    cp_tile(g_Blo, n0, k0, sdst + 3 * TILE_BYTES, tid);
}

__global__ void __launch_bounds__(256, 1)
topkast_gemm_k(const float* __restrict__ bias, float* __restrict__ out) {
    extern __shared__ char smem[];
    const uint32_t sbase = smem_u32(smem);
    const uint32_t tile_base = (sbase + 32 + 1023) & ~1023u;
    const int tid = threadIdx.x;
    const int wid = tid >> 5;
    const int lane = tid & 31;
    const int m0 = blockIdx.y * 128;
    const int n0 = blockIdx.x * 128;

    const int wm = (wid & 3) * 32;
    const int wn = (wid >> 2) * 64;

    float acc[2][8][4];
#pragma unroll
    for (int a = 0; a < 2; ++a)
#pragma unroll
        for (int bq = 0; bq < 8; ++bq)
#pragma unroll
            for (int r = 0; r < 4; ++r) acc[a][bq][r] = 0.0f;

    cp_chunk(0, tile_base, m0, n0, tid);
    cp_commit();

    for (int c = 0; c < NCHUNK; ++c) {
        cp_wait0();
        __syncthreads();
        if (c + 1 < NCHUNK) {
            cp_chunk(c + 1, tile_base + (uint32_t)((c + 1) & 1) * STAGE_BYTES,
                     m0, n0, tid);
            cp_commit();
        }
        const uint32_t b = tile_base + (uint32_t)(c & 1) * STAGE_BYTES;

#pragma unroll
        for (int ks = 0; ks < 4; ++ks) {
            uint32_t ahf[2][4], alf[2][4], bhf[4][4], blf[4][4];
            {
                uint32_t arow = (uint32_t)(wm + (lane & 15));
                uint32_t k8 = (uint32_t)(ks * 2 + (lane >> 4));
#pragma unroll
                for (int mt = 0; mt < 2; ++mt) {
                    uint32_t off = (arow + mt * 16) * 128 + k8 * 16;
                    off ^= (off >> 3) & 0x70;
                    ldm_x4(ahf[mt], b + off);
                    ldm_x4(alf[mt], b + TILE_BYTES + off);
                }
            }
            {
                uint32_t nrow = (uint32_t)(wn + ((lane >> 4) << 3) + (lane & 7));
                uint32_t k8 = (uint32_t)(ks * 2 + ((lane >> 3) & 1));
#pragma unroll
                for (int np = 0; np < 4; ++np) {
                    uint32_t off = (nrow + np * 16) * 128 + k8 * 16;
                    off ^= (off >> 3) & 0x70;
                    ldm_x4(bhf[np], b + 2 * TILE_BYTES + off);
                    ldm_x4(blf[np], b + 3 * TILE_BYTES + off);
                }
            }
#pragma unroll
            for (int mt = 0; mt < 2; ++mt) {
#pragma unroll
                for (int ng = 0; ng < 8; ++ng) {
                    const uint32_t* bh = &bhf[ng >> 1][(ng & 1) * 2];
                    const uint32_t* bl = &blf[ng >> 1][(ng & 1) * 2];
                    mma_bf16(acc[mt][ng], ahf[mt], bh);
                    mma_bf16(acc[mt][ng], alf[mt], bh);
                    mma_bf16(acc[mt][ng], ahf[mt], bl);
                }
            }
        }
    }

#pragma unroll
    for (int mt = 0; mt < 2; ++mt) {
#pragma unroll
        for (int ng = 0; ng < 8; ++ng) {
            int m = m0 + wm + mt * 16 + (lane >> 2);
            int n = n0 + wn + ng * 8 + (lane & 3) * 2;
            float bx = bias[n], by = bias[n + 1];
            float2 v0 = make_float2(acc[mt][ng][0] + bx, acc[mt][ng][1] + by);
            float2 v1 = make_float2(acc[mt][ng][2] + bx, acc[mt][ng][3] + by);
            *reinterpret_cast<float2*>(&out[(size_t)m * NOUT + n]) = v0;
            *reinterpret_cast<float2*>(&out[(size_t)(m + 8) * NOUT + n]) = v1;
        }
    }
}
#endif

// ---------------- entry -----------------------------------------------------
extern "C" void kernel_launch(void* const* d_in, const int* in_sizes, int n_in,
                              void* d_out, int out_size) {
    const float* inputs = nullptr;
    const float* weight = nullptr;
    const float* bias = nullptr;
    for (int i = 0; i < n_in; ++i) {
        if (in_sizes[i] == NROWS * KDIM)      inputs = (const float*)d_in[i];
        else if (in_sizes[i] == NOUT * KDIM)  weight = (const float*)d_in[i];
        else if (in_sizes[i] == NOUT)         bias   = (const float*)d_in[i];
    }
    float* out = (float*)d_out;

    const int w4 = NOUT * KDIM / 4;

    zero_hists_k<<<256, 256>>>();
    hist_pass1_k<<<2048, 256>>>((const float4*)weight, w4);
    select_pass1_k<<<1, 256>>>();
    hist_pass2_k<<<2048, 256>>>((const float4*)weight, w4);
    select_pass2_k<<<1, 256>>>();

    conv_inputs_k<<<8192, 256>>>((const float4*)inputs);
    conv_weight_k<<<4096, 256>>>((const float4*)weight);

    cudaFuncSetAttribute(topkast_gemm_k,
                         cudaFuncAttributeMaxDynamicSharedMemorySize, GEMM_SMEM);
    dim3 grid(NOUT / 128, NROWS / 128);   // (32, 64)
    topkast_gemm_k<<<grid, 256, GEMM_SMEM>>>(bias, out);

    (void)out_size;
}

// round 11
// speedup vs baseline: 1.1915x; 1.1100x over previous
#include <cuda_runtime.h>
#include <cuda_bf16.h>
#include <cstdint>
#include <cstddef>

#define DI __device__ __forceinline__

static constexpr int NROWS = 8192;   // rows of inputs (M)
static constexpr int KDIM  = 4096;   // inner dim (K)
static constexpr int NOUT  = 4096;   // output features (N)
// index = f32(0.9) * f32(16777215) rounds to exactly 15099493.0 -> frac = 0,
// thresh = ascending order statistic at 0-based rank 15099493 of |w|.
static constexpr unsigned long long QRANK = 15099493ull;

// ---------------- scratch (device globals; no allocation allowed) ----------
__device__ __align__(16) unsigned short g_Ahi[(size_t)NROWS * KDIM];
__device__ __align__(16) unsigned short g_Alo[(size_t)NROWS * KDIM];
__device__ __align__(16) unsigned short g_Bhi[(size_t)NOUT * KDIM];
__device__ __align__(16) unsigned short g_Blo[(size_t)NOUT * KDIM];
__device__ unsigned g_hist1[65536];
__device__ unsigned g_hist2[65536];
__device__ unsigned g_sel[2];        // [0] = hi16 bucket, [1] = remaining rank
__device__ unsigned g_threshbits;    // f32 bit pattern of |w| threshold

// ---------------- small PTX helpers ----------------------------------------
DI uint32_t smem_u32(const void* p) {
    uint32_t r;
    asm("{ .reg .u64 t; cvta.to.shared.u64 t, %1; cvt.u32.u64 %0, t; }"
        : "=r"(r) : "l"(p));
    return r;
}

DI void cp16(uint32_t sdst, const void* gsrc) {
    asm volatile("cp.async.cg.shared.global [%0], [%1], 16;"
                 :: "r"(sdst), "l"(gsrc) : "memory");
}
DI void cp_commit() { asm volatile("cp.async.commit_group;" ::: "memory"); }
DI void cp_wait0()  { asm volatile("cp.async.wait_group 0;" ::: "memory"); }

DI void ldm_x4(uint32_t* r, uint32_t addr) {
    asm volatile("ldmatrix.sync.aligned.m8n8.x4.shared.b16 {%0,%1,%2,%3}, [%4];"
                 : "=r"(r[0]), "=r"(r[1]), "=r"(r[2]), "=r"(r[3]) : "r"(addr));
}

DI void mma_bf16(float* d, const uint32_t* a, const uint32_t* b) {
    asm volatile(
        "mma.sync.aligned.m16n8k16.row.col.f32.bf16.bf16.f32 "
        "{%0,%1,%2,%3}, {%4,%5,%6,%7}, {%8,%9}, {%0,%1,%2,%3};"
        : "+f"(d[0]), "+f"(d[1]), "+f"(d[2]), "+f"(d[3])
        : "r"(a[0]), "r"(a[1]), "r"(a[2]), "r"(a[3]), "r"(b[0]), "r"(b[1]));
}

DI uint32_t elect_one() {
    uint32_t p;
    asm volatile(
        "{\n\t.reg .pred p;\n\t"
        "elect.sync _|p, 0xFFFFFFFF;\n\t"
        "selp.b32 %0, 1, 0, p;\n\t}"
        : "=r"(p));
    return p;
}

DI void mbar_init(uint32_t addr, uint32_t count) {
    asm volatile("mbarrier.init.shared.b64 [%0], %1;"
                 :: "r"(addr), "r"(count) : "memory");
}

DI void mbar_wait_parity(uint32_t addr, uint32_t parity) {
    asm volatile(
        "{\n\t.reg .pred P1;\n\t"
        "WAIT_LOOP_%=:\n\t"
        "mbarrier.try_wait.parity.acquire.cta.shared::cta.b64 P1, [%0], %1, 0x989680;\n\t"
        "@P1 bra.uni WAIT_DONE_%=;\n\t"
        "bra.uni WAIT_LOOP_%=;\n\t"
        "WAIT_DONE_%=:\n\t}"
        :: "r"(addr), "r"(parity) : "memory");
}

// ---------------- threshold: exact order statistic via 2-pass radix --------
__global__ void zero_hists_k() {
    int i = blockIdx.x * blockDim.x + threadIdx.x;
    if (i < 65536) { g_hist1[i] = 0u; g_hist2[i] = 0u; }
}

__global__ void hist_pass1_k(const float4* __restrict__ w, int n4) {
    for (int i = blockIdx.x * blockDim.x + threadIdx.x; i < n4;
         i += gridDim.x * blockDim.x) {
        float4 v = w[i];
        atomicAdd(&g_hist1[__float_as_uint(fabsf(v.x)) >> 16], 1u);
        atomicAdd(&g_hist1[__float_as_uint(fabsf(v.y)) >> 16], 1u);
        atomicAdd(&g_hist1[__float_as_uint(fabsf(v.z)) >> 16], 1u);
        atomicAdd(&g_hist1[__float_as_uint(fabsf(v.w)) >> 16], 1u);
    }
}

__global__ void select_pass1_k() {
    __shared__ unsigned partial[256];
    unsigned tid = threadIdx.x;
    unsigned sum = 0;
    for (int j = 0; j < 256; j++) sum += g_hist1[tid * 256 + j];
    partial[tid] = sum;
    __syncthreads();
    if (tid == 0) {
        unsigned long long cum = 0;
        int seg = 0;
        for (; seg < 256; seg++) {
            if (cum + partial[seg] > QRANK) break;
            cum += partial[seg];
        }
        unsigned b = seg * 256;
        for (int j = 0; j < 256; j++) {
            unsigned h = g_hist1[seg * 256 + j];
            if (cum + h > QRANK) { b = seg * 256 + j; break; }
            cum += h;
        }
        g_sel[0] = b;
        g_sel[1] = (unsigned)(QRANK - cum);
    }
}

__global__ void hist_pass2_k(const float4* __restrict__ w, int n4) {
    unsigned bucket = g_sel[0];
    for (int i = blockIdx.x * blockDim.x + threadIdx.x; i < n4;
         i += gridDim.x * blockDim.x) {
        float4 v = w[i];
        unsigned u;
        u = __float_as_uint(fabsf(v.x)); if ((u >> 16) == bucket) atomicAdd(&g_hist2[u & 0xFFFFu], 1u);
        u = __float_as_uint(fabsf(v.y)); if ((u >> 16) == bucket) atomicAdd(&g_hist2[u & 0xFFFFu], 1u);
        u = __float_as_uint(fabsf(v.z)); if ((u >> 16) == bucket) atomicAdd(&g_hist2[u & 0xFFFFu], 1u);
        u = __float_as_uint(fabsf(v.w)); if ((u >> 16) == bucket) atomicAdd(&g_hist2[u & 0xFFFFu], 1u);
    }
}

__global__ void select_pass2_k() {
    __shared__ unsigned partial[256];
    unsigned tid = threadIdx.x;
    unsigned sum = 0;
    for (int j = 0; j < 256; j++) sum += g_hist2[tid * 256 + j];
    partial[tid] = sum;
    __syncthreads();
    if (tid == 0) {
        unsigned long long rank = g_sel[1];
        unsigned long long cum = 0;
        int seg = 0;
        for (; seg < 256; seg++) {
            if (cum + partial[seg] > rank) break;
            cum += partial[seg];
        }
        unsigned lo = seg * 256;
        for (int j = 0; j < 256; j++) {
            unsigned h = g_hist2[seg * 256 + j];
            if (cum + h > rank) { lo = seg * 256 + j; break; }
            cum += h;
        }
        g_threshbits = (g_sel[0] << 16) | lo;
    }
}

// ---------------- split-bf16 conversion ------------------------------------
DI void split_bf16(float f, unsigned short& h, unsigned short& l) {
    __nv_bfloat16 hb = __float2bfloat16(f);                 // RN
    float rest = f - __bfloat162float(hb);                  // exact
    __nv_bfloat16 lb = __float2bfloat16(rest);
    h = __bfloat16_as_ushort(hb);
    l = __bfloat16_as_ushort(lb);
}

__global__ void conv_inputs_k(const float4* __restrict__ x) {
    const size_t n4 = (size_t)NROWS * KDIM / 4;
    for (size_t i = blockIdx.x * (size_t)blockDim.x + threadIdx.x; i < n4;
         i += (size_t)gridDim.x * blockDim.x) {
        float4 v = x[i];
        ushort4 h, l;
        split_bf16(v.x, h.x, l.x);
        split_bf16(v.y, h.y, l.y);
        split_bf16(v.z, h.z, l.z);
        split_bf16(v.w, h.w, l.w);
        reinterpret_cast<ushort4*>(g_Ahi)[i] = h;
        reinterpret_cast<ushort4*>(g_Alo)[i] = l;
    }
}

__global__ void conv_weight_k(const float4* __restrict__ w) {
    const unsigned tb = g_threshbits;
    const size_t n4 = (size_t)NOUT * KDIM / 4;
    for (size_t i = blockIdx.x * (size_t)blockDim.x + threadIdx.x; i < n4;
         i += (size_t)gridDim.x * blockDim.x) {
        float4 v = w[i];
        float m0 = (__float_as_uint(fabsf(v.x)) >= tb) ? v.x : 0.0f;
        float m1 = (__float_as_uint(fabsf(v.y)) >= tb) ? v.y : 0.0f;
        float m2 = (__float_as_uint(fabsf(v.z)) >= tb) ? v.z : 0.0f;
        float m3 = (__float_as_uint(fabsf(v.w)) >= tb) ? v.w : 0.0f;
        ushort4 h, l;
        split_bf16(m0, h.x, l.x);
        split_bf16(m1, h.y, l.y);
        split_bf16(m2, h.z, l.z);
        split_bf16(m3, h.w, l.w);
        reinterpret_cast<ushort4*>(g_Bhi)[i] = h;
        reinterpret_cast<ushort4*>(g_Blo)[i] = l;
    }
}

// ---------------- GEMM (dual path) ------------------------------------------
// Tile: 128(M) x 128(N), K chunks of 64. 4 smem tiles (Ahi/Alo/Bhi/Blo),
// each 128 rows x 128B (SW128 swizzle), double buffered.
static constexpr int TILE_BYTES  = 128 * 128;                 // 16 KB
static constexpr int STAGE_BYTES = 4 * TILE_BYTES;            // 64 KB
static constexpr unsigned GEMM_SMEM = 2048 + 2 * STAGE_BYTES; // 130 KB (covers both paths)
static constexpr int NCHUNK = KDIM / 64;                      // 64

#if defined(__CUDA_ARCH__) && defined(__CUDA_ARCH_FEAT_SM103_ALL)
// ========== tcgen05 path: 256 threads, double-buffered (R10-proven core) =====
// R10 proved: LDG+STS -> sync -> fence.proxy.async -> kind::f16 MMA -> commit
// -> mbar wait -> LDTM epilogue is correct. R11 overlaps load(c+1) with the
// async MMA(c): the only remaining wait (MMA c-1 done before overwriting its
// buffer) is off the critical path.

// idesc (kind::f16): dtype F32, a/b BF16, N=128, M=128
static constexpr uint32_t GEMM_IDESC =
    (1u << 4) | (1u << 7) | (1u << 10) | ((128u / 8) << 17) | ((128u / 16) << 24);

DI unsigned long long make_desc(uint32_t addr) {
    // SW128 K-major: layout=2, version=1, SBO=64, LBO=1
    return 0x4000404000010000ULL | ((unsigned long long)(addr >> 4) & 0x3FFFULL);
}

DI void ld_tile(const unsigned short* __restrict__ g, int r0, int k0,
                char* sdst, int tid) {
#pragma unroll
    for (int t = 0; t < 4; ++t) {
        int i = t * 256 + tid;           // 0..1023
        int row = i >> 3;                // 0..127
        int c16 = i & 7;                 // 16B column within 128B row
        uint4 v = reinterpret_cast<const uint4*>(
                      g + (size_t)(r0 + row) * KDIM + k0)[c16];
        uint32_t off = (uint32_t)(row * 128 + c16 * 16);
        off ^= (off >> 3) & 0x70;        // SW128 swizzle
        *reinterpret_cast<uint4*>(sdst + off) = v;
    }
}

DI void ld_chunk(int c, char* dst, int m0, int n0, int tid) {
    const int k0 = c * 64;
    ld_tile(g_Ahi, m0, k0, dst, tid);
    ld_tile(g_Alo, m0, k0, dst + TILE_BYTES, tid);
    ld_tile(g_Bhi, n0, k0, dst + 2 * TILE_BYTES, tid);
    ld_tile(g_Blo, n0, k0, dst + 3 * TILE_BYTES, tid);
}

DI void mma_f16(uint32_t d_tmem, unsigned long long a_desc,
                unsigned long long b_desc, uint32_t en) {
    uint32_t z = 0u;
    asm volatile(
        "{\n\t.reg .pred p;\n\t"
        "setp.ne.u32 p, %5, 0;\n\t"
        "tcgen05.mma.cta_group::1.kind::f16 [%0], %1, %2, %3, {%4,%4,%4,%4}, p;\n\t}"
        :: "r"(d_tmem), "l"(a_desc), "l"(b_desc), "r"(GEMM_IDESC),
           "r"(z), "r"(en) : "memory");
}

__global__ void __launch_bounds__(256, 1)
topkast_gemm_k(const float* __restrict__ bias, float* __restrict__ out) {
    extern __shared__ char smem[];
    const uint32_t sbase = smem_u32(smem);
    const uint32_t tile_base = (sbase + 32 + 1023) & ~1023u;
    char* tiles = smem + (tile_base - sbase);
    const uint32_t mbar0 = sbase + 8;
    const uint32_t mbar1 = sbase + 16;
    const int tid = threadIdx.x;
    const int wid = tid >> 5;
    const int lid = tid & 31;
    const int m0 = blockIdx.y * 128;
    const int n0 = blockIdx.x * 128;

    // Alloc 128 TMEM cols from warp 0 only; no relinquish (warps that later
    // tcgen05.ld must keep the permit). D occupies cols 0..127.
    if (wid == 0) {
        asm volatile(
            "tcgen05.alloc.cta_group::1.sync.aligned.shared::cta.b32 [%0], %1;"
            :: "r"(sbase), "r"(128u) : "memory");
    }
    if (tid == 0) { mbar_init(mbar0, 1); mbar_init(mbar1, 1); }
    __syncthreads();

    uint32_t tmem;
    asm volatile("ld.shared.b32 %0, [%1];" : "=r"(tmem) : "r"(sbase));
    uint32_t leader = (wid == 0) ? elect_one() : 0u;

    // prologue: chunk 0 into buffer 0
    ld_chunk(0, tiles, m0, n0, tid);
    __syncthreads();
    asm volatile("fence.proxy.async.shared::cta;" ::: "memory");

    for (int c = 0; c < NCHUNK; ++c) {
        // chunk c is resident & fenced in buffer c&1
        if (leader) {
            uint32_t boff = tile_base + (uint32_t)(c & 1) * STAGE_BYTES;
            unsigned long long dAh = make_desc(boff);
            unsigned long long dAl = make_desc(boff + TILE_BYTES);
            unsigned long long dBh = make_desc(boff + 2 * TILE_BYTES);
            unsigned long long dBl = make_desc(boff + 3 * TILE_BYTES);
#pragma unroll
            for (int ks = 0; ks < 4; ++ks)
                mma_f16(tmem, dAh + 2 * ks, dBh + 2 * ks,
                        (c == 0 && ks == 0) ? 0u : 1u);
#pragma unroll
            for (int ks = 0; ks < 4; ++ks)
                mma_f16(tmem, dAh + 2 * ks, dBl + 2 * ks, 1u);
#pragma unroll
            for (int ks = 0; ks < 4; ++ks)
                mma_f16(tmem, dAl + 2 * ks, dBh + 2 * ks, 1u);
            asm volatile(
                "tcgen05.commit.cta_group::1.mbarrier::arrive::one.shared::cluster.b64 [%0];"
                :: "r"((c & 1) ? mbar1 : mbar0) : "memory");
        }
        if (c + 1 < NCHUNK) {
            if (c >= 1) {
                // buffer (c+1)&1 holds chunk c-1; wait for MMA(c-1)'s commit.
                // mbar[(c-1)&1], completed-phase parity ((c-1)>>1)&1.
                mbar_wait_parity(((c - 1) & 1) ? mbar1 : mbar0,
                                 (uint32_t)(((c - 1) >> 1) & 1));
            }
            ld_chunk(c + 1, tiles + (size_t)((c + 1) & 1) * STAGE_BYTES,
                     m0, n0, tid);
            __syncthreads();
            asm volatile("fence.proxy.async.shared::cta;" ::: "memory");
        }
    }

    // chunk 63 is the 32nd commit on mbar1 -> completed phase 31, parity 1
    mbar_wait_parity(mbar1, 1u);
    asm volatile("tcgen05.fence::after_thread_sync;" ::: "memory");

    // epilogue: warp w -> subpartition rows (w&3)*32, column half (w>>2)*64
    {
        const int m = m0 + (wid & 3) * 32 + lid;
        const int ch = (wid >> 2) * 64;
        float4* orow = reinterpret_cast<float4*>(out + (size_t)m * NOUT + n0);
        const float4* brow = reinterpret_cast<const float4*>(bias + n0);
#pragma unroll
        for (int q = 0; q < 2; ++q) {
            const int cb = ch + q * 32;
            uint32_t r[32];
            asm volatile(
                "tcgen05.ld.sync.aligned.32x32b.x32.b32 "
                "{%0, %1, %2, %3, %4, %5, %6, %7, "
                " %8, %9, %10, %11, %12, %13, %14, %15, "
                " %16, %17, %18, %19, %20, %21, %22, %23, "
                " %24, %25, %26, %27, %28, %29, %30, %31}, [%32];"
                : "=r"(r[0]), "=r"(r[1]), "=r"(r[2]), "=r"(r[3]),
                  "=r"(r[4]), "=r"(r[5]), "=r"(r[6]), "=r"(r[7]),
                  "=r"(r[8]), "=r"(r[9]), "=r"(r[10]), "=r"(r[11]),
                  "=r"(r[12]), "=r"(r[13]), "=r"(r[14]), "=r"(r[15]),
                  "=r"(r[16]), "=r"(r[17]), "=r"(r[18]), "=r"(r[19]),
                  "=r"(r[20]), "=r"(r[21]), "=r"(r[22]), "=r"(r[23]),
                  "=r"(r[24]), "=r"(r[25]), "=r"(r[26]), "=r"(r[27]),
                  "=r"(r[28]), "=r"(r[29]), "=r"(r[30]), "=r"(r[31])
                : "r"(tmem + cb));
            asm volatile("tcgen05.wait::ld.sync.aligned;" ::: "memory");
#pragma unroll
            for (int j = 0; j < 8; ++j) {
                float4 bv = brow[cb / 4 + j];
                float4 v;
                v.x = __uint_as_float(r[4 * j + 0]) + bv.x;
                v.y = __uint_as_float(r[4 * j + 1]) + bv.y;
                v.z = __uint_as_float(r[4 * j + 2]) + bv.z;
                v.w = __uint_as_float(r[4 * j + 3]) + bv.w;
                orow[cb / 4 + j] = v;
            }
        }
    }
    asm volatile("tcgen05.fence::before_thread_sync;" ::: "memory");
    __syncthreads();
    if (wid == 0) {
        asm volatile("tcgen05.dealloc.cta_group::1.sync.aligned.b32 %0, %1;"
                     :: "r"(tmem), "r"(128u));
    }
}

#else
// ===================== mma.sync fallback: 256 threads (R5-proven) ============
DI void cp_tile(const unsigned short* __restrict__ g, int r0, int k0,
                uint32_t sdst, int tid) {
#pragma unroll
    for (int t = 0; t < 4; ++t) {
        int i = t * 256 + tid;           // 0..1023
        int row = i >> 3;
        int c16 = i & 7;
        const char* src =
            (const char*)(g + (size_t)(r0 + row) * KDIM + k0) + c16 * 16;
        uint32_t off = (uint32_t)(row * 128 + c16 * 16);
        off ^= (off >> 3) & 0x70;
        cp16(sdst + off, src);
    }
}

DI void cp_chunk(int c, uint32_t sdst, int m0, int n0, int tid) {
    int k0 = c * 64;
    cp_tile(g_Ahi, m0, k0, sdst, tid);
    cp_tile(g_Alo, m0, k0, sdst + TILE_BYTES, tid);
    cp_tile(g_Bhi, n0, k0, sdst + 2 * TILE_BYTES, tid);
    cp_tile(g_Blo, n0, k0, sdst + 3 * TILE_BYTES, tid);
}

__global__ void __launch_bounds__(256, 1)
topkast_gemm_k(const float* __restrict__ bias, float* __restrict__ out) {
    extern __shared__ char smem[];
    const uint32_t sbase = smem_u32(smem);
    const uint32_t tile_base = (sbase + 32 + 1023) & ~1023u;
    const int tid = threadIdx.x;
    const int wid = tid >> 5;
    const int lane = tid & 31;
    const int m0 = blockIdx.y * 128;
    const int n0 = blockIdx.x * 128;

    const int wm = (wid & 3) * 32;
    const int wn = (wid >> 2) * 64;

    float acc[2][8][4];
#pragma unroll
    for (int a = 0; a < 2; ++a)
#pragma unroll
        for (int bq = 0; bq < 8; ++bq)
#pragma unroll
            for (int r = 0; r < 4; ++r) acc[a][bq][r] = 0.0f;

    cp_chunk(0, tile_base, m0, n0, tid);
    cp_commit();

    for (int c = 0; c < NCHUNK; ++c) {
        cp_wait0();
        __syncthreads();
        if (c + 1 < NCHUNK) {
            cp_chunk(c + 1, tile_base + (uint32_t)((c + 1) & 1) * STAGE_BYTES,
                     m0, n0, tid);
            cp_commit();
        }
        const uint32_t b = tile_base + (uint32_t)(c & 1) * STAGE_BYTES;

#pragma unroll
        for (int ks = 0; ks < 4; ++ks) {
            uint32_t ahf[2][4], alf[2][4], bhf[4][4], blf[4][4];
            {
                uint32_t arow = (uint32_t)(wm + (lane & 15));
                uint32_t k8 = (uint32_t)(ks * 2 + (lane >> 4));
#pragma unroll
                for (int mt = 0; mt < 2; ++mt) {
                    uint32_t off = (arow + mt * 16) * 128 + k8 * 16;
                    off ^= (off >> 3) & 0x70;
                    ldm_x4(ahf[mt], b + off);
                    ldm_x4(alf[mt], b + TILE_BYTES + off);
                }
            }
            {
                uint32_t nrow = (uint32_t)(wn + ((lane >> 4) << 3) + (lane & 7));
                uint32_t k8 = (uint32_t)(ks * 2 + ((lane >> 3) & 1));
#pragma unroll
                for (int np = 0; np < 4; ++np) {
                    uint32_t off = (nrow + np * 16) * 128 + k8 * 16;
                    off ^= (off >> 3) & 0x70;
                    ldm_x4(bhf[np], b + 2 * TILE_BYTES + off);
                    ldm_x4(blf[np], b + 3 * TILE_BYTES + off);
                }
            }
#pragma unroll
            for (int mt = 0; mt < 2; ++mt) {
#pragma unroll
                for (int ng = 0; ng < 8; ++ng) {
                    const uint32_t* bh = &bhf[ng >> 1][(ng & 1) * 2];
                    const uint32_t* bl = &blf[ng >> 1][(ng & 1) * 2];
                    mma_bf16(acc[mt][ng], ahf[mt], bh);
                    mma_bf16(acc[mt][ng], alf[mt], bh);
                    mma_bf16(acc[mt][ng], ahf[mt], bl);
                }
            }
        }
    }

#pragma unroll
    for (int mt = 0; mt < 2; ++mt) {
#pragma unroll
        for (int ng = 0; ng < 8; ++ng) {
            int m = m0 + wm + mt * 16 + (lane >> 2);
            int n = n0 + wn + ng * 8 + (lane & 3) * 2;
            float bx = bias[n], by = bias[n + 1];
            float2 v0 = make_float2(acc[mt][ng][0] + bx, acc[mt][ng][1] + by);
            float2 v1 = make_float2(acc[mt][ng][2] + bx, acc[mt][ng][3] + by);
            *reinterpret_cast<float2*>(&out[(size_t)m * NOUT + n]) = v0;
            *reinterpret_cast<float2*>(&out[(size_t)(m + 8) * NOUT + n]) = v1;
        }
    }
}
#endif

// ---------------- entry -----------------------------------------------------
extern "C" void kernel_launch(void* const* d_in, const int* in_sizes, int n_in,
                              void* d_out, int out_size) {
    const float* inputs = nullptr;
    const float* weight = nullptr;
    const float* bias = nullptr;
    for (int i = 0; i < n_in; ++i) {
        if (in_sizes[i] == NROWS * KDIM)      inputs = (const float*)d_in[i];
        else if (in_sizes[i] == NOUT * KDIM)  weight = (const float*)d_in[i];
        else if (in_sizes[i] == NOUT)         bias   = (const float*)d_in[i];
    }
    float* out = (float*)d_out;

    const int w4 = NOUT * KDIM / 4;

    zero_hists_k<<<256, 256>>>();
    hist_pass1_k<<<2048, 256>>>((const float4*)weight, w4);
    select_pass1_k<<<1, 256>>>();
    hist_pass2_k<<<2048, 256>>>((const float4*)weight, w4);
    select_pass2_k<<<1, 256>>>();

    conv_inputs_k<<<8192, 256>>>((const float4*)inputs);
    conv_weight_k<<<4096, 256>>>((const float4*)weight);

    cudaFuncSetAttribute(topkast_gemm_k,
                         cudaFuncAttributeMaxDynamicSharedMemorySize, GEMM_SMEM);
    dim3 grid(NOUT / 128, NROWS / 128);   // (32, 64)
    topkast_gemm_k<<<grid, 256, GEMM_SMEM>>>(bias, out);

    (void)out_size;
}